// round 11
// baseline (speedup 1.0000x reference)
#include <cuda_runtime.h>

#define NW  17
#define PAD 20
#define TPB 128

// Overflow/underflow-safe fast tanh: 1 - 2/(1 + 2^(2*log2(e)*x))
__device__ __forceinline__ float ex2_approx(float x) {
    float y; asm("ex2.approx.f32 %0, %1;" : "=f"(y) : "f"(x)); return y;
}
__device__ __forceinline__ float rcp_approx(float x) {
    float y; asm("rcp.approx.f32 %0, %1;" : "=f"(y) : "f"(x)); return y;
}
__device__ __forceinline__ float fast_tanh(float x) {
    float e = ex2_approx(x * 2.8853900817779268f);   // 2*log2(e)
    return fmaf(-2.0f, rcp_approx(e + 1.0f), 1.0f);
}

// acc[j] (+)= sum_k v[k] * W[k][j]   -- W rows 16B aligned, float4 LDS
template <bool INIT>
__device__ __forceinline__ void matvec(float acc[NW], const float v[NW],
                                       const float W[NW][PAD]) {
#pragma unroll
    for (int k = 0; k < NW; ++k) {
        const float vk = v[k];
        const float4* w4 = reinterpret_cast<const float4*>(W[k]);
#pragma unroll
        for (int q = 0; q < 4; ++q) {
            float4 w = w4[q];
            if (INIT && k == 0) {
                acc[4*q+0] = vk * w.x;
                acc[4*q+1] = vk * w.y;
                acc[4*q+2] = vk * w.z;
                acc[4*q+3] = vk * w.w;
            } else {
                acc[4*q+0] = fmaf(vk, w.x, acc[4*q+0]);
                acc[4*q+1] = fmaf(vk, w.y, acc[4*q+1]);
                acc[4*q+2] = fmaf(vk, w.z, acc[4*q+2]);
                acc[4*q+3] = fmaf(vk, w.w, acc[4*q+3]);
            }
        }
        if (INIT && k == 0) acc[16] = vk * W[k][16];
        else                acc[16] = fmaf(vk, W[k][16], acc[16]);
    }
}

__device__ __forceinline__ void feat(float v[NW], float s,
                                     const float* sWf, const float* sbf) {
#pragma unroll
    for (int j = 0; j < NW; ++j) v[j] = fast_tanh(fmaf(s, sWf[j], sbf[j]));
}

// NOTE: no minBlocksPerMultiprocessor clause. R6/R8/R10 proved that
// __launch_bounds__(128, 3) (reg cap 170) makes ptxas demote arrays to
// local memory -> DRAM 50%, issue 10%, 4x slower than the uncapped R3.
// At <=168 regs the HW gives 3 CTAs/SM naturally; forcing it only hurts.
extern "C" __global__ void __launch_bounds__(TPB)
mp_kernel(const float* __restrict__ inp,
          const float* __restrict__ Wf,  const float* __restrict__ bf,
          const float* __restrict__ Wm,  const float* __restrict__ bm,
          const float* __restrict__ Wu,  const float* __restrict__ bu,
          const float* __restrict__ Wr,  const float* __restrict__ br,
          float* __restrict__ out, int B)
{
    __shared__ __align__(16) float sM1[NW][PAD];   // Wm[:17]   (P projection)
    __shared__ __align__(16) float sM2[NW][PAD];   // Wm[17:34] (Q projection)
    __shared__ __align__(16) float sU1[NW][PAD];   // Wu[:17]
    __shared__ __align__(16) float sU2[NW][PAD];   // Wu[17:34]
    __shared__ __align__(16) float sU34[NW][PAD];  // Wu[34:51] + Wu[51:68]
    __shared__ float sWf[NW], sbf[NW], sbm[NW], sbu[NW], sWr[5 * NW], sbr;

    for (int idx = threadIdx.x; idx < NW * NW; idx += TPB) {
        int k = idx / NW, j = idx % NW;
        sM1[k][j]  = Wm[idx];
        sM2[k][j]  = Wm[NW * NW + idx];
        sU1[k][j]  = Wu[idx];
        sU2[k][j]  = Wu[NW * NW + idx];
        sU34[k][j] = Wu[2 * NW * NW + idx] + Wu[3 * NW * NW + idx];
    }
    if (threadIdx.x < NW) {
        sWf[threadIdx.x] = Wf[threadIdx.x];
        sbf[threadIdx.x] = bf[threadIdx.x];
        sbm[threadIdx.x] = bm[threadIdx.x];
        sbu[threadIdx.x] = bu[threadIdx.x];
    }
    for (int idx = threadIdx.x; idx < 5 * NW; idx += TPB) sWr[idx] = Wr[idx];
    if (threadIdx.x == 0) sbr = br[0];
    __syncthreads();

    const int row = blockIdx.x * TPB + threadIdx.x;
    if (row >= B) return;

    const float x0 = inp[row * 5 + 0];
    const float x1 = inp[row * 5 + 1];
    const float x2 = inp[row * 5 + 2];
    const float x3 = inp[row * 5 + 3];
    const float x4 = inp[row * 5 + 4];

    float o = sbr;

    // One node fully retired at a time; nothing held across nodes except the
    // readout scalar. Q projections recomputed per use (+19% FLOPs) to keep
    // the scheduled live set small.
    // node x: m1 = tanh(Px + Q_next + bm) @ U1 ; m2 = tanh(Px + Q_prev + bm) @ U2
#define DO_NODE(X, XN, XP, WOFF)                                            \
    {                                                                       \
        float v[NW], P[NW], acc[NW], Q[NW], m[NW];                          \
        feat(v, X, sWf, sbf);                                               \
        matvec<true>(P, v, sM1);                                            \
        _Pragma("unroll")                                                   \
        for (int j = 0; j < NW; ++j) acc[j] = sbu[j];                       \
        matvec<false>(acc, v, sU34);                                        \
        feat(v, XN, sWf, sbf);                                              \
        matvec<true>(Q, v, sM2);                                            \
        _Pragma("unroll")                                                   \
        for (int j = 0; j < NW; ++j) m[j] = fast_tanh(P[j] + Q[j] + sbm[j]);\
        matvec<false>(acc, m, sU1);                                         \
        feat(v, XP, sWf, sbf);                                              \
        matvec<true>(Q, v, sM2);                                            \
        _Pragma("unroll")                                                   \
        for (int j = 0; j < NW; ++j) m[j] = fast_tanh(P[j] + Q[j] + sbm[j]);\
        matvec<false>(acc, m, sU2);                                         \
        _Pragma("unroll")                                                   \
        for (int j = 0; j < NW; ++j)                                        \
            o = fmaf(fast_tanh(acc[j]), sWr[(WOFF) + j], o);                \
    }

    DO_NODE(x0, x1, x3, 0)        // a: Mab -> U1, Mad -> U2
    DO_NODE(x1, x0, x2, NW)       // b: Mba -> U1, Mbc -> U2
    DO_NODE(x2, x1, x3, 2 * NW)   // c: Mcb -> U1, Mcd -> U2
    DO_NODE(x3, x2, x0, 3 * NW)   // d: Mdc -> U1, Mda -> U2
#undef DO_NODE

    // ---- node e: Ue = tanh(e@U34 + bu) ----
    {
        float v[NW], acc[NW];
        feat(v, x4, sWf, sbf);
#pragma unroll
        for (int j = 0; j < NW; ++j) acc[j] = sbu[j];
        matvec<false>(acc, v, sU34);
#pragma unroll
        for (int j = 0; j < NW; ++j)
            o = fmaf(fast_tanh(acc[j]), sWr[4 * NW + j], o);
    }

    out[row] = o;
}

extern "C" void kernel_launch(void* const* d_in, const int* in_sizes, int n_in,
                              void* d_out, int out_size)
{
    const float* inp = (const float*)d_in[0];
    const float* Wf  = (const float*)d_in[1];
    const float* bf  = (const float*)d_in[2];
    const float* Wm  = (const float*)d_in[3];
    const float* bm  = (const float*)d_in[4];
    const float* Wu  = (const float*)d_in[5];
    const float* bu  = (const float*)d_in[6];
    const float* Wr  = (const float*)d_in[7];
    const float* br  = (const float*)d_in[8];
    float* out = (float*)d_out;

    const int B = in_sizes[0] / 5;
    const int grid = (B + TPB - 1) / TPB;
    mp_kernel<<<grid, TPB>>>(inp, Wf, bf, Wm, bm, Wu, bu, Wr, br, out, B);
}

// round 12
// speedup vs baseline: 4.1357x; 4.1357x over previous
#include <cuda_runtime.h>

#define NW  17
#define PAD 20
#define TPB 128

// Overflow/underflow-safe fast tanh: 1 - 2/(1 + 2^(2*log2(e)*x))
__device__ __forceinline__ float ex2_approx(float x) {
    float y; asm("ex2.approx.f32 %0, %1;" : "=f"(y) : "f"(x)); return y;
}
__device__ __forceinline__ float rcp_approx(float x) {
    float y; asm("rcp.approx.f32 %0, %1;" : "=f"(y) : "f"(x)); return y;
}
__device__ __forceinline__ float fast_tanh(float x) {
    float e = ex2_approx(x * 2.8853900817779268f);   // 2*log2(e)
    return fmaf(-2.0f, rcp_approx(e + 1.0f), 1.0f);
}

// acc[j] (+)= sum_k v[k] * W[k][j]   -- W rows 16B aligned, float4 LDS
template <bool INIT>
__device__ __forceinline__ void matvec(float acc[NW], const float v[NW],
                                       const float W[NW][PAD]) {
#pragma unroll
    for (int k = 0; k < NW; ++k) {
        const float vk = v[k];
        const float4* w4 = reinterpret_cast<const float4*>(W[k]);
#pragma unroll
        for (int q = 0; q < 4; ++q) {
            float4 w = w4[q];
            if (INIT && k == 0) {
                acc[4*q+0] = vk * w.x;
                acc[4*q+1] = vk * w.y;
                acc[4*q+2] = vk * w.z;
                acc[4*q+3] = vk * w.w;
            } else {
                acc[4*q+0] = fmaf(vk, w.x, acc[4*q+0]);
                acc[4*q+1] = fmaf(vk, w.y, acc[4*q+1]);
                acc[4*q+2] = fmaf(vk, w.z, acc[4*q+2]);
                acc[4*q+3] = fmaf(vk, w.w, acc[4*q+3]);
            }
        }
        if (INIT && k == 0) acc[16] = vk * W[k][16];
        else                acc[16] = fmaf(vk, W[k][16], acc[16]);
    }
}

__device__ __forceinline__ void feat(float v[NW], float s,
                                     const float* sWf, const float* sbf) {
#pragma unroll
    for (int j = 0; j < NW; ++j) v[j] = fast_tanh(fmaf(s, sWf[j], sbf[j]));
}

// m[j] = tanh(P[j] + Q[j] + bm[j])
__device__ __forceinline__ void mkmsg(float m[NW], const float P[NW],
                                      const float Q[NW], const float* sbm) {
#pragma unroll
    for (int j = 0; j < NW; ++j) m[j] = fast_tanh(P[j] + Q[j] + sbm[j]);
}

// Structure deliberately mirrors the PROVEN R0 kernel (255 regs, DRAM=2%,
// 1282us): straight-line code, all arrays named at function scope, no
// macro scopes, no launch-bounds occupancy clause (R6-R11 showed every
// restructure/cap produced local-memory demotion: DRAM 36-52%, ~5x slower).
// Only change vs R0: node order a,b,d,c with EARLY RETIREMENT -- each acc
// and its P/Q die as soon as that node's two edges complete, lowering peak
// register pressure without changing the matvec count (21/row).
extern "C" __global__ void __launch_bounds__(TPB)
mp_kernel(const float* __restrict__ inp,
          const float* __restrict__ Wf,  const float* __restrict__ bf,
          const float* __restrict__ Wm,  const float* __restrict__ bm,
          const float* __restrict__ Wu,  const float* __restrict__ bu,
          const float* __restrict__ Wr,  const float* __restrict__ br,
          float* __restrict__ out, int B)
{
    __shared__ __align__(16) float sM1[NW][PAD];   // Wm[:17]   (P projection)
    __shared__ __align__(16) float sM2[NW][PAD];   // Wm[17:34] (Q projection)
    __shared__ __align__(16) float sU1[NW][PAD];   // Wu[:17]
    __shared__ __align__(16) float sU2[NW][PAD];   // Wu[17:34]
    __shared__ __align__(16) float sU34[NW][PAD];  // Wu[34:51] + Wu[51:68]
    __shared__ float sWf[NW], sbf[NW], sbm[NW], sbu[NW], sWr[5 * NW], sbr;

    for (int idx = threadIdx.x; idx < NW * NW; idx += TPB) {
        int k = idx / NW, j = idx % NW;
        sM1[k][j]  = Wm[idx];
        sM2[k][j]  = Wm[NW * NW + idx];
        sU1[k][j]  = Wu[idx];
        sU2[k][j]  = Wu[NW * NW + idx];
        sU34[k][j] = Wu[2 * NW * NW + idx] + Wu[3 * NW * NW + idx];
    }
    if (threadIdx.x < NW) {
        sWf[threadIdx.x] = Wf[threadIdx.x];
        sbf[threadIdx.x] = bf[threadIdx.x];
        sbm[threadIdx.x] = bm[threadIdx.x];
        sbu[threadIdx.x] = bu[threadIdx.x];
    }
    for (int idx = threadIdx.x; idx < 5 * NW; idx += TPB) sWr[idx] = Wr[idx];
    if (threadIdx.x == 0) sbr = br[0];
    __syncthreads();

    const int row = blockIdx.x * TPB + threadIdx.x;
    if (row >= B) return;

    const float x0 = inp[row * 5 + 0];
    const float x1 = inp[row * 5 + 1];
    const float x2 = inp[row * 5 + 2];
    const float x3 = inp[row * 5 + 3];
    const float x4 = inp[row * 5 + 4];

    float v[NW], m[NW];
    float Pa[NW], Qa[NW], Pb[NW], Qb[NW];
    float Pc[NW], Qc[NW], Pd[NW], Qd[NW];
    float accA[NW], accB[NW], accC[NW], accD[NW];
    float o = sbr;

    // ---- node a ----
    feat(v, x0, sWf, sbf);
    matvec<true>(Pa, v, sM1);
    matvec<true>(Qa, v, sM2);
#pragma unroll
    for (int j = 0; j < NW; ++j) accA[j] = sbu[j];
    matvec<false>(accA, v, sU34);

    // ---- node b ----
    feat(v, x1, sWf, sbf);
    matvec<true>(Pb, v, sM1);
    matvec<true>(Qb, v, sM2);
#pragma unroll
    for (int j = 0; j < NW; ++j) accB[j] = sbu[j];
    matvec<false>(accB, v, sU34);

    // ---- edges a-b ----
    mkmsg(m, Pa, Qb, sbm); matvec<false>(accA, m, sU1);   // Mab
    mkmsg(m, Pb, Qa, sbm); matvec<false>(accB, m, sU1);   // Mba

    // ---- node d ----
    feat(v, x3, sWf, sbf);
    matvec<true>(Pd, v, sM1);
    matvec<true>(Qd, v, sM2);
#pragma unroll
    for (int j = 0; j < NW; ++j) accD[j] = sbu[j];
    matvec<false>(accD, v, sU34);

    // ---- edges a-d: completes accA -> retire node a ----
    mkmsg(m, Pa, Qd, sbm); matvec<false>(accA, m, sU2);   // Mad (Pa dies)
    mkmsg(m, Pd, Qa, sbm); matvec<false>(accD, m, sU2);   // Mda (Qa dies)
#pragma unroll
    for (int j = 0; j < NW; ++j)
        o = fmaf(fast_tanh(accA[j]), sWr[j], o);          // accA dies

    // ---- node c ----
    feat(v, x2, sWf, sbf);
    matvec<true>(Pc, v, sM1);
    matvec<true>(Qc, v, sM2);
#pragma unroll
    for (int j = 0; j < NW; ++j) accC[j] = sbu[j];
    matvec<false>(accC, v, sU34);

    // ---- edges b-c: completes accB -> retire node b ----
    mkmsg(m, Pb, Qc, sbm); matvec<false>(accB, m, sU2);   // Mbc (Pb dies)
    mkmsg(m, Pc, Qb, sbm); matvec<false>(accC, m, sU1);   // Mcb (Qb dies)
#pragma unroll
    for (int j = 0; j < NW; ++j)
        o = fmaf(fast_tanh(accB[j]), sWr[NW + j], o);     // accB dies

    // ---- edges c-d: completes accC and accD -> retire both ----
    mkmsg(m, Pc, Qd, sbm); matvec<false>(accC, m, sU2);   // Mcd (Pc, Qd die)
    mkmsg(m, Pd, Qc, sbm); matvec<false>(accD, m, sU1);   // Mdc (Pd, Qc die)
#pragma unroll
    for (int j = 0; j < NW; ++j)
        o = fmaf(fast_tanh(accC[j]), sWr[2 * NW + j], o);
#pragma unroll
    for (int j = 0; j < NW; ++j)
        o = fmaf(fast_tanh(accD[j]), sWr[3 * NW + j], o);

    // ---- node e: Ue = tanh(e@U34 + bu) ----
    feat(v, x4, sWf, sbf);
#pragma unroll
    for (int j = 0; j < NW; ++j) accA[j] = sbu[j];        // reuse accA
    matvec<false>(accA, v, sU34);
#pragma unroll
    for (int j = 0; j < NW; ++j)
        o = fmaf(fast_tanh(accA[j]), sWr[4 * NW + j], o);

    out[row] = o;
}

extern "C" void kernel_launch(void* const* d_in, const int* in_sizes, int n_in,
                              void* d_out, int out_size)
{
    const float* inp = (const float*)d_in[0];
    const float* Wf  = (const float*)d_in[1];
    const float* bf  = (const float*)d_in[2];
    const float* Wm  = (const float*)d_in[3];
    const float* bm  = (const float*)d_in[4];
    const float* Wu  = (const float*)d_in[5];
    const float* bu  = (const float*)d_in[6];
    const float* Wr  = (const float*)d_in[7];
    const float* br  = (const float*)d_in[8];
    float* out = (float*)d_out;

    const int B = in_sizes[0] / 5;
    const int grid = (B + TPB - 1) / TPB;
    mp_kernel<<<grid, TPB>>>(inp, Wf, bf, Wm, bm, Wu, bu, Wr, br, out, B);
}

// round 14
// speedup vs baseline: 7.0709x; 1.7097x over previous
#include <cuda_runtime.h>

#define NW   17
#define NK   18     // padded k rows (row 17 zeroed)
#define CPAD 24     // padded col stride: j<9 -> col j ; j>=9 -> col j+3 (12..20)
#define JH   9      // j elements per thread (half, padded)
#define TPB  128

__device__ __forceinline__ float ex2_approx(float x) {
    float y; asm("ex2.approx.f32 %0, %1;" : "=f"(y) : "f"(x)); return y;
}
__device__ __forceinline__ float rcp_approx(float x) {
    float y; asm("rcp.approx.f32 %0, %1;" : "=f"(y) : "f"(x)); return y;
}
__device__ __forceinline__ float fast_tanh(float x) {
    float e = ex2_approx(x * 2.8853900817779268f);   // 2*log2(e)
    return fmaf(-2.0f, rcp_approx(e + 1.0f), 1.0f);
}

// Split-output matvec with FULL input vector v (no shuffles):
// acc[jj] (+)= sum_{k<17} v[k] * W[k][jb+jj]
template <bool INIT>
__device__ __forceinline__ void matvec_v(float acc[JH], const float v[NW],
                                         const float W[NK][CPAD], int jb) {
#pragma unroll
    for (int k = 0; k < NW; ++k) {
        const float vk = v[k];
        const float4* w4 = reinterpret_cast<const float4*>(&W[k][jb]);
        float4 w0 = w4[0], w1 = w4[1];
        float  w2 = W[k][jb + 8];
        if (INIT && k == 0) {
            acc[0] = vk * w0.x; acc[1] = vk * w0.y; acc[2] = vk * w0.z; acc[3] = vk * w0.w;
            acc[4] = vk * w1.x; acc[5] = vk * w1.y; acc[6] = vk * w1.z; acc[7] = vk * w1.w;
            acc[8] = vk * w2;
        } else {
            acc[0] = fmaf(vk, w0.x, acc[0]); acc[1] = fmaf(vk, w0.y, acc[1]);
            acc[2] = fmaf(vk, w0.z, acc[2]); acc[3] = fmaf(vk, w0.w, acc[3]);
            acc[4] = fmaf(vk, w1.x, acc[4]); acc[5] = fmaf(vk, w1.y, acc[5]);
            acc[6] = fmaf(vk, w1.z, acc[6]); acc[7] = fmaf(vk, w1.w, acc[7]);
            acc[8] = fmaf(vk, w2,   acc[8]);
        }
    }
}

// Split-output matvec with SPLIT input vector m (shuffle-gather from the pair):
// acc[jj] += sum_{k<18} m_full[k] * W[k][jb+jj], m_full gathered via shfl.
__device__ __forceinline__ void matvec_m(float acc[JH], const float mloc[JH],
                                         const float W[NK][CPAD], int jb,
                                         int srcE, int srcO) {
#pragma unroll
    for (int k = 0; k < NK; ++k) {
        const float mk = __shfl_sync(0xffffffffu, mloc[k % JH], (k < JH) ? srcE : srcO);
        const float4* w4 = reinterpret_cast<const float4*>(&W[k][jb]);
        float4 w0 = w4[0], w1 = w4[1];
        float  w2 = W[k][jb + 8];
        acc[0] = fmaf(mk, w0.x, acc[0]); acc[1] = fmaf(mk, w0.y, acc[1]);
        acc[2] = fmaf(mk, w0.z, acc[2]); acc[3] = fmaf(mk, w0.w, acc[3]);
        acc[4] = fmaf(mk, w1.x, acc[4]); acc[5] = fmaf(mk, w1.y, acc[5]);
        acc[6] = fmaf(mk, w1.z, acc[6]); acc[7] = fmaf(mk, w1.w, acc[7]);
        acc[8] = fmaf(mk, w2,   acc[8]);
    }
}

__device__ __forceinline__ void feat(float v[NW], float s,
                                     const float* sWf, const float* sbf) {
#pragma unroll
    for (int j = 0; j < NW; ++j) v[j] = fast_tanh(fmaf(s, sWf[j], sbf[j]));
}

// 2 threads per row (even: j=0..8, odd: j=9..16+pad). Halves per-thread
// register state -- R0/R12 proved 1-thread-per-row pins at 255 regs (spills,
// occ 12.5%, issue 28%), and every pressure-reduction attempt triggered
// local-mem demotion (R6-R11, DRAM ~50%). Dividing the row is the only
// remaining axis. No min-blocks clause (proven harmful).
extern "C" __global__ void __launch_bounds__(TPB)
mp_kernel(const float* __restrict__ inp,
          const float* __restrict__ Wf,  const float* __restrict__ bf,
          const float* __restrict__ Wm,  const float* __restrict__ bm,
          const float* __restrict__ Wu,  const float* __restrict__ bu,
          const float* __restrict__ Wr,  const float* __restrict__ br,
          float* __restrict__ out, int B)
{
    __shared__ __align__(16) float sM1[NK][CPAD];   // Wm[:17]
    __shared__ __align__(16) float sM2[NK][CPAD];   // Wm[17:34]
    __shared__ __align__(16) float sU1[NK][CPAD];   // Wu[:17]
    __shared__ __align__(16) float sU2[NK][CPAD];   // Wu[17:34]
    __shared__ __align__(16) float sU34[NK][CPAD];  // Wu[34:51]+Wu[51:68]
    __shared__ float sWf[NW], sbf[NW];
    __shared__ __align__(16) float sbm_s[CPAD], sbu_s[CPAD], sWr_s[5 * CPAD];
    __shared__ float sbr;

    const int tid = threadIdx.x;

    // Zero everything padded first (pads MUST be 0 for correctness).
    for (int idx = tid; idx < NK * CPAD; idx += TPB) {
        int k = idx / CPAD, c = idx % CPAD;
        sM1[k][c] = 0.f; sM2[k][c] = 0.f;
        sU1[k][c] = 0.f; sU2[k][c] = 0.f; sU34[k][c] = 0.f;
    }
    for (int idx = tid; idx < CPAD; idx += TPB) { sbm_s[idx] = 0.f; sbu_s[idx] = 0.f; }
    for (int idx = tid; idx < 5 * CPAD; idx += TPB) sWr_s[idx] = 0.f;
    __syncthreads();

    for (int idx = tid; idx < NW * NW; idx += TPB) {
        int k = idx / NW, j = idx % NW;
        int c = (j < JH) ? j : j + 3;
        sM1[k][c]  = Wm[idx];
        sM2[k][c]  = Wm[NW * NW + idx];
        sU1[k][c]  = Wu[idx];
        sU2[k][c]  = Wu[NW * NW + idx];
        sU34[k][c] = Wu[2 * NW * NW + idx] + Wu[3 * NW * NW + idx];
    }
    if (tid < NW) {
        sWf[tid] = Wf[tid]; sbf[tid] = bf[tid];
        int c = (tid < JH) ? tid : tid + 3;
        sbm_s[c] = bm[tid]; sbu_s[c] = bu[tid];
    }
    for (int idx = tid; idx < 5 * NW; idx += TPB) {
        int n = idx / NW, j = idx % NW;
        int c = (j < JH) ? j : j + 3;
        sWr_s[n * CPAD + c] = Wr[idx];
    }
    if (tid == 0) sbr = br[0];
    __syncthreads();

    const int gtid = blockIdx.x * TPB + tid;
    const int row  = gtid >> 1;
    if (row >= B) return;

    const int lane = tid & 31;
    const int srcE = lane & ~1, srcO = srcE | 1;
    const int half = tid & 1;
    const int jb   = half * 12;     // col base: 0 (j 0..8) or 12 (j 9..16+pad)

    const float x0 = inp[row * 5 + 0];
    const float x1 = inp[row * 5 + 1];
    const float x2 = inp[row * 5 + 2];
    const float x3 = inp[row * 5 + 3];
    const float x4 = inp[row * 5 + 4];

    float o = half ? 0.f : sbr;
    float v[NW], m[JH];
    float Pa[JH], Qa[JH], Pb[JH], Qb[JH], Pc[JH], Qc[JH], Pd[JH], Qd[JH];
    float accA[JH], accB[JH], accC[JH], accD[JH];

    // ---- node a ----
    feat(v, x0, sWf, sbf);
    matvec_v<true>(Pa, v, sM1, jb);
    matvec_v<true>(Qa, v, sM2, jb);
#pragma unroll
    for (int jj = 0; jj < JH; ++jj) accA[jj] = sbu_s[jb + jj];
    matvec_v<false>(accA, v, sU34, jb);

    // ---- node b ----
    feat(v, x1, sWf, sbf);
    matvec_v<true>(Pb, v, sM1, jb);
    matvec_v<true>(Qb, v, sM2, jb);
#pragma unroll
    for (int jj = 0; jj < JH; ++jj) accB[jj] = sbu_s[jb + jj];
    matvec_v<false>(accB, v, sU34, jb);

    // ---- edges a-b ----
#pragma unroll
    for (int jj = 0; jj < JH; ++jj) m[jj] = fast_tanh(Pa[jj] + Qb[jj] + sbm_s[jb + jj]);
    matvec_m(accA, m, sU1, jb, srcE, srcO);                 // Mab
#pragma unroll
    for (int jj = 0; jj < JH; ++jj) m[jj] = fast_tanh(Pb[jj] + Qa[jj] + sbm_s[jb + jj]);
    matvec_m(accB, m, sU1, jb, srcE, srcO);                 // Mba

    // ---- node d ----
    feat(v, x3, sWf, sbf);
    matvec_v<true>(Pd, v, sM1, jb);
    matvec_v<true>(Qd, v, sM2, jb);
#pragma unroll
    for (int jj = 0; jj < JH; ++jj) accD[jj] = sbu_s[jb + jj];
    matvec_v<false>(accD, v, sU34, jb);

    // ---- edges a-d: retire node a ----
#pragma unroll
    for (int jj = 0; jj < JH; ++jj) m[jj] = fast_tanh(Pa[jj] + Qd[jj] + sbm_s[jb + jj]);
    matvec_m(accA, m, sU2, jb, srcE, srcO);                 // Mad (Pa dies)
#pragma unroll
    for (int jj = 0; jj < JH; ++jj) m[jj] = fast_tanh(Pd[jj] + Qa[jj] + sbm_s[jb + jj]);
    matvec_m(accD, m, sU2, jb, srcE, srcO);                 // Mda (Qa dies)
#pragma unroll
    for (int jj = 0; jj < JH; ++jj)
        o = fmaf(fast_tanh(accA[jj]), sWr_s[jb + jj], o);   // accA dies

    // ---- node c ----
    feat(v, x2, sWf, sbf);
    matvec_v<true>(Pc, v, sM1, jb);
    matvec_v<true>(Qc, v, sM2, jb);
#pragma unroll
    for (int jj = 0; jj < JH; ++jj) accC[jj] = sbu_s[jb + jj];
    matvec_v<false>(accC, v, sU34, jb);

    // ---- edges b-c: retire node b ----
#pragma unroll
    for (int jj = 0; jj < JH; ++jj) m[jj] = fast_tanh(Pb[jj] + Qc[jj] + sbm_s[jb + jj]);
    matvec_m(accB, m, sU2, jb, srcE, srcO);                 // Mbc (Pb dies)
#pragma unroll
    for (int jj = 0; jj < JH; ++jj) m[jj] = fast_tanh(Pc[jj] + Qb[jj] + sbm_s[jb + jj]);
    matvec_m(accC, m, sU1, jb, srcE, srcO);                 // Mcb (Qb dies)
#pragma unroll
    for (int jj = 0; jj < JH; ++jj)
        o = fmaf(fast_tanh(accB[jj]), sWr_s[CPAD + jb + jj], o);  // accB dies

    // ---- edges c-d: retire nodes c and d ----
#pragma unroll
    for (int jj = 0; jj < JH; ++jj) m[jj] = fast_tanh(Pc[jj] + Qd[jj] + sbm_s[jb + jj]);
    matvec_m(accC, m, sU2, jb, srcE, srcO);                 // Mcd
#pragma unroll
    for (int jj = 0; jj < JH; ++jj) m[jj] = fast_tanh(Pd[jj] + Qc[jj] + sbm_s[jb + jj]);
    matvec_m(accD, m, sU1, jb, srcE, srcO);                 // Mdc
#pragma unroll
    for (int jj = 0; jj < JH; ++jj)
        o = fmaf(fast_tanh(accC[jj]), sWr_s[2 * CPAD + jb + jj], o);
#pragma unroll
    for (int jj = 0; jj < JH; ++jj)
        o = fmaf(fast_tanh(accD[jj]), sWr_s[3 * CPAD + jb + jj], o);

    // ---- node e ----
    feat(v, x4, sWf, sbf);
#pragma unroll
    for (int jj = 0; jj < JH; ++jj) accA[jj] = sbu_s[jb + jj];   // reuse accA
    matvec_v<false>(accA, v, sU34, jb);
#pragma unroll
    for (int jj = 0; jj < JH; ++jj)
        o = fmaf(fast_tanh(accA[jj]), sWr_s[4 * CPAD + jb + jj], o);

    // ---- pair reduction: even lane writes ----
    o += __shfl_xor_sync(0xffffffffu, o, 1);
    if (!half) out[row] = o;
}

extern "C" void kernel_launch(void* const* d_in, const int* in_sizes, int n_in,
                              void* d_out, int out_size)
{
    const float* inp = (const float*)d_in[0];
    const float* Wf  = (const float*)d_in[1];
    const float* bf  = (const float*)d_in[2];
    const float* Wm  = (const float*)d_in[3];
    const float* bm  = (const float*)d_in[4];
    const float* Wu  = (const float*)d_in[5];
    const float* bu  = (const float*)d_in[6];
    const float* Wr  = (const float*)d_in[7];
    const float* br  = (const float*)d_in[8];
    float* out = (float*)d_out;

    const int B = in_sizes[0] / 5;
    const long long threads = 2LL * B;
    const int grid = (int)((threads + TPB - 1) / TPB);
    mp_kernel<<<grid, TPB>>>(inp, Wf, bf, Wm, bm, Wu, bu, Wr, br, out, B);
}